// round 16
// baseline (speedup 1.0000x reference)
#include <cuda_runtime.h>
#include <math.h>

#define NG 16
#define GS 16384
#define NCTA 8
#define NT 512
#define FULL 0xffffffffu

__device__ float g_A [NG*GS];
__device__ float g_h [NG*GS];
__device__ float g_hb[NG*GS];
__device__ float g_x2[NG*GS];
__device__ float g_S [NG*GS];
__device__ float g_B [NG*GS];
__device__ float g_wtg[NG*12*GS];
__device__ float g_w1tg[NG*640*128];
__device__ float g_xs[NG*640];
__device__ float g_fit[NG*128];
__device__ float g_fa[NG*128];
__device__ float g_fb[NG*128];
__device__ float g_fc[NG*128];
__device__ unsigned g_bar[NG*32];

// smem carve (floats)
#define O_H    0        // 16384
#define O_W    16384    // 32768 (W1/A @ +0, W2/Acol @ +16384)
#define O_AC   49152    // 2048
#define O_AG   51200    // 2112 (16 x 132)
#define O_RED  53312    // 1024
#define O_SA   54336    // 128
#define O_DEG  54464    // 32
#define O_PERM 54496    // 128 ints
#define SMF    54624

__device__ __forceinline__ void gbar(int g,int slot,int tid){
  __syncthreads();
  if (tid==0){
    __threadfence();
    unsigned* p=&g_bar[g*32+slot];
    atomicAdd(p,1u);
    unsigned v;
    do{ asm volatile("ld.acquire.gpu.u32 %0,[%1];":"=r"(v):"l"(p):"memory"); }while(v<NCTA);
  }
  __syncthreads();
}
__device__ __forceinline__ float wsum(float v){
#pragma unroll
  for(int o=16;o;o>>=1) v+=__shfl_xor_sync(FULL,v,o);
  return v;
}
__device__ __forceinline__ float wmax(float v){
#pragma unroll
  for(int o=16;o;o>>=1) v=fmaxf(v,__shfl_xor_sync(FULL,v,o));
  return v;
}
__device__ __forceinline__ void fma4(float4&o,float a,const float4 w){
  o.x=fmaf(a,w.x,o.x);o.y=fmaf(a,w.y,o.y);o.z=fmaf(a,w.z,o.z);o.w=fmaf(a,w.w,o.w);
}
__device__ __forceinline__ float dot4(const float4 a,const float4 b){
  return a.x*b.x+a.y*b.y+a.z*b.z+a.w*b.w;
}

// dense smem-broadcast matmul, float4 operand fetch (rows 16B-aligned, stride 132)
__device__ __forceinline__ void dense_bc4(const float* W,const float* g0,const float* g1,
                                          int c0,float4&O0,float4&O1){
  for(int k4=0;k4<32;++k4){
    float4 a0=*(const float4*)&g0[k4*4];
    float4 a1=*(const float4*)&g1[k4*4];
    const float* wb=&W[k4*4*128+c0];
    float4 wv;
    wv=*(const float4*)(wb     ); fma4(O0,a0.x,wv); fma4(O1,a1.x,wv);
    wv=*(const float4*)(wb+128 ); fma4(O0,a0.y,wv); fma4(O1,a1.y,wv);
    wv=*(const float4*)(wb+256 ); fma4(O0,a0.z,wv); fma4(O1,a1.z,wv);
    wv=*(const float4*)(wb+384 ); fma4(O0,a0.w,wv); fma4(O1,a1.w,wv);
  }
}

// ---------------- warp bitonic top-k into smem (descending, ties -> lower index) ----------------
__device__ void dv_topk_sort(int* sp,int g,int lane,int n,int k){
  unsigned long long key[4];
#pragma unroll
  for(int q=0;q<4;++q){
    int idx=q*32+lane;
    float f=(idx<n)?__ldcg(g_fit+g*128+idx):0.f;
    unsigned fb=__float_as_uint(f);
    key[q]=((unsigned long long)fb<<32)|(unsigned)(127-idx);
  }
  for(int size=2;size<=128;size<<=1){
    for(int stride=size>>1;stride>0;stride>>=1){
      if(stride>=32){
        int qs=stride>>5;
#pragma unroll
        for(int q=0;q<4;++q){
          if((q&qs)==0){
            int qb=q|qs;
            int idxa=q*32+lane;
            bool up=((idxa&size)!=0);
            unsigned long long a=key[q],b=key[qb];
            unsigned long long mx=(a>b)?a:b, mn=(a>b)?b:a;
            key[q]=up?mn:mx; key[qb]=up?mx:mn;
          }
        }
      }else{
#pragma unroll
        for(int q=0;q<4;++q){
          int idx=q*32+lane;
          unsigned long long pv=__shfl_xor_sync(FULL,key[q],stride);
          bool up=((idx&size)!=0);
          bool lower=((idx&stride)==0);
          bool takeMax=(lower!=up);
          unsigned long long mx=(key[q]>pv)?key[q]:pv;
          unsigned long long mn=(key[q]>pv)?pv:key[q];
          key[q]=takeMax?mx:mn;
        }
      }
    }
  }
#pragma unroll
  for(int q=0;q<4;++q){
    int pos=q*32+lane;
    if(pos<k){
      int idx=127-(int)(key[q]&0xFFFFFFFFu);
      sp[pos]=idx;
    }
  }
}

// ---------------- conv ----------------
__device__ void dv_conv(float* sm,int g,int r,int tid,const float* __restrict__ X,int Cin,
                        float* __restrict__ hout,const float* __restrict__ wt1,
                        const float* __restrict__ wt2,const float* __restrict__ brel,
                        int slot,int n,float invn,int wH){
  float* sH=sm+O_H; float* sW=sm+O_W; float* sAc=sm+O_AC; float* sAg=sm+O_AG;
  float* sRed=sm+O_RED; float* sDeg=sm+O_DEG;
  int lane=tid&31,w=tid>>5,c0=lane*4;
  int p=w&7,hf=w>>3;
  int j0=r*16,jr0=2*p,jr1=jr0+1,jA=j0+jr0,jB=j0+jr1;
  const float* Ab=g_A+g*GS;

  if(Cin==128&&n==128){
    for(int i4=tid;i4<4096;i4+=NT) ((float4*)sH)[i4]=__ldcg((const float4*)X+i4);
  }else{
    for(int idx=tid;idx<16384;idx+=NT){
      int i=idx>>7,c=idx&127;
      float v=0.f;
      if(i<n&&c<Cin) v=(Cin==128)?__ldcg(X+i*128+c):__ldg(X+i*64+c);
      sH[idx]=v;
    }
  }
  for(int idx=tid;idx<2048;idx+=NT){
    int i=idx>>4,jr=idx&15,j=j0+jr;
    sAc[idx]=(i<n&&j<n)?__ldcg(Ab+i*128+j):0.f;
  }
  for(int i4=tid;i4<4096;i4+=NT) ((float4*)sW)[i4]=__ldg((const float4*)wt1+i4);
  for(int i4=tid;i4<4096;i4+=NT) ((float4*)(sW+16384))[i4]=__ldg((const float4*)wt2+i4);
  __syncthreads();

  int ilo=hf*64;
  unsigned m0p[2],m1p[2],mu[2];
#pragma unroll
  for(int u=0;u<2;++u){
    int i=ilo+32*u+lane;
    float2 av=*(const float2*)&sAc[i*16+jr0];
    m0p[u]=__ballot_sync(FULL,av.x!=0.f);
    m1p[u]=__ballot_sync(FULL,av.y!=0.f);
    mu[u]=m0p[u]|m1p[u];
  }
  float cd0=(float)(__popc(m0p[0])+__popc(m0p[1]));
  float cd1=(float)(__popc(m1p[0])+__popc(m1p[1]));
  float4 A0={0,0,0,0},A1={0,0,0,0};
#pragma unroll
  for(int u=0;u<2;++u){
    unsigned m=mu[u];
    while(m){
      int b=__ffs(m)-1; m&=m-1;
      int i=ilo+32*u+b;
      float2 av=*(const float2*)&sAc[i*16+jr0];
      float4 hv=*(const float4*)&sH[i*128+c0];
      fma4(A0,av.x,hv); fma4(A1,av.y,hv);
    }
  }
  float4 H0={0,0,0,0},H1={0,0,0,0};
  if(hf==1){
    *(float4*)&sAg[jr0*132+c0]=A0;
    *(float4*)&sAg[jr1*132+c0]=A1;
    int ja=(jA<n)?jA:0,jb=(jB<n)?jB:0;
    H0=*(const float4*)&sH[ja*128+c0];
    H1=*(const float4*)&sH[jb*128+c0];
  }
  if(lane==0){ sDeg[hf*16+jr0]=cd0; sDeg[hf*16+jr1]=cd1; }
  __syncthreads();
  if(hf==0){
    float4 P0=*(const float4*)&sAg[jr0*132+c0];
    float4 P1=*(const float4*)&sAg[jr1*132+c0];
    float id0=1.f/fmaxf(sDeg[jr0]+sDeg[16+jr0],1.f);
    float id1=1.f/fmaxf(sDeg[jr1]+sDeg[16+jr1],1.f);
    A0.x=(A0.x+P0.x)*id0;A0.y=(A0.y+P0.y)*id0;A0.z=(A0.z+P0.z)*id0;A0.w=(A0.w+P0.w)*id0;
    A1.x=(A1.x+P1.x)*id1;A1.y=(A1.y+P1.y)*id1;A1.z=(A1.z+P1.z)*id1;A1.w=(A1.w+P1.w)*id1;
    *(float4*)&sAg[jr0*132+c0]=A0;
    *(float4*)&sAg[jr1*132+c0]=A1;
  }
  __syncwarp();

  float4 O0={0,0,0,0},O1={0,0,0,0};
  if(w<8){
    dense_bc4(sW,&sAg[jr0*132],&sAg[jr1*132],c0,O0,O1);
  }else{
    float hr0[4]={H0.x,H0.y,H0.z,H0.w};
    float hr1[4]={H1.x,H1.y,H1.z,H1.w};
    for(int kl=0;kl<32;++kl){
#pragma unroll
      for(int comp=0;comp<4;++comp){
        float a0=__shfl_sync(FULL,hr0[comp],kl);
        float a1=__shfl_sync(FULL,hr1[comp],kl);
        float4 wv=*(const float4*)&sW[16384+(kl*4+comp)*128+c0];
        fma4(O0,a0,wv); fma4(O1,a1,wv);
      }
    }
    *(float4*)&sAc[jr0*128+c0]=O0;
    *(float4*)&sAc[jr1*128+c0]=O1;
  }
  __syncthreads();
  if(w<8){
    float4 P0=*(const float4*)&sAc[jr0*128+c0];
    float4 P1=*(const float4*)&sAc[jr1*128+c0];
    float4 bb=__ldg((const float4*)(brel+c0));
    float4 V0,V1;
    V0.x=fmaxf(O0.x+P0.x+bb.x,0.f);V0.y=fmaxf(O0.y+P0.y+bb.y,0.f);
    V0.z=fmaxf(O0.z+P0.z+bb.z,0.f);V0.w=fmaxf(O0.w+P0.w+bb.w,0.f);
    V1.x=fmaxf(O1.x+P1.x+bb.x,0.f);V1.y=fmaxf(O1.y+P1.y+bb.y,0.f);
    V1.z=fmaxf(O1.z+P1.z+bb.z,0.f);V1.w=fmaxf(O1.w+P1.w+bb.w,0.f);
    if(jA<n){ if(wH) *(float4*)&hout[jA*128+c0]=V0; } else V0=make_float4(0,0,0,0);
    if(jB<n){ if(wH) *(float4*)&hout[jB*128+c0]=V1; } else V1=make_float4(0,0,0,0);
    float4 P; P.x=V0.x+V1.x;P.y=V0.y+V1.y;P.z=V0.z+V1.z;P.w=V0.w+V1.w;
    *(float4*)&sRed[p*128+c0]=P;
  }
  __syncthreads();
  if(tid<128){
    float s=0.f;
#pragma unroll
    for(int q=0;q<8;++q) s+=sRed[q*128+tid];
    atomicAdd(&g_xs[g*640+slot*128+tid],s*invn);
  }
}

// ---------------- fused poolq + softmax + x_new + fitness prep ----------------
__device__ void dv_pqsm(float* sm,int g,int r,int tid,const float* __restrict__ hg,
                        const float* __restrict__ wt,const float* __restrict__ linb,
                        const float* __restrict__ attw,const float* __restrict__ attbp,
                        const float* __restrict__ le1w,const float* __restrict__ le1bp,
                        const float* __restrict__ le2w,const float* __restrict__ le3w,int n){
  float* sH=sm+O_H; float* sW=sm+O_W; float* sAc=sm+O_AC; float* sAg=sm+O_AG; float* sax=sm+O_SA;
  int lane=tid&31,w=tid>>5,c0=lane*4;
  int p=w&7;
  int j0=r*16,jr0=2*p,jr1=jr0+1,jA=j0+jr0,jB=j0+jr1;
  const float* Ab=g_A+g*GS;

  for(int idx=tid;idx<16384;idx+=NT){
    int i=idx>>7;
    sH[idx]=(i<n)?__ldcg(hg+idx):0.f;
  }
  for(int idx=tid;idx<2048;idx+=NT){
    int i=idx>>4,jr=idx&15,j=j0+jr;
    sAc[idx]=(i<n&&j<n)?__ldcg(Ab+i*128+j):0.f;
  }
  for(int i4=tid;i4<4096;i4+=NT) ((float4*)sW)[i4]=__ldg((const float4*)wt+i4);
  __syncthreads();

  float aq0=0.f,aq1=0.f;
  unsigned ma[4],mb[4];
  if(w<8){
#pragma unroll
    for(int u=0;u<4;++u){
      int i=32*u+lane;
      float2 av=*(const float2*)&sAc[i*16+jr0];
      bool b0=(i<n)&&(jA<n)&&((av.x!=0.f)||(i==jA));
      bool b1=(i<n)&&(jB<n)&&((av.y!=0.f)||(i==jB));
      ma[u]=__ballot_sync(FULL,b0);
      mb[u]=__ballot_sync(FULL,b1);
    }
    float4 M0=make_float4(-1e30f,-1e30f,-1e30f,-1e30f),M1=M0;
#pragma unroll
    for(int u=0;u<4;++u){
      unsigned m=ma[u]|mb[u];
      while(m){
        int b=__ffs(m)-1; m&=m-1;
        int i=32*u+b;
        float4 hv=*(const float4*)&sH[i*128+c0];
        if((ma[u]>>b)&1){M0.x=fmaxf(M0.x,hv.x);M0.y=fmaxf(M0.y,hv.y);M0.z=fmaxf(M0.z,hv.z);M0.w=fmaxf(M0.w,hv.w);}
        if((mb[u]>>b)&1){M1.x=fmaxf(M1.x,hv.x);M1.y=fmaxf(M1.y,hv.y);M1.z=fmaxf(M1.z,hv.z);M1.w=fmaxf(M1.w,hv.w);}
      }
    }
    *(float4*)&sAg[jr0*132+c0]=M0;
    *(float4*)&sAg[jr1*132+c0]=M1;
    __syncwarp();
    float4 Q0={0,0,0,0},Q1={0,0,0,0};
    dense_bc4(sW,&sAg[jr0*132],&sAg[jr1*132],c0,Q0,Q1);
    float4 lb=__ldg((const float4*)(linb+c0));
    Q0.x+=lb.x;Q0.y+=lb.y;Q0.z+=lb.z;Q0.w+=lb.w;
    Q1.x+=lb.x;Q1.y+=lb.y;Q1.z+=lb.z;Q1.w+=lb.w;
    float4 awq=__ldg((const float4*)(attw+c0));
    aq0=wsum(dot4(Q0,awq));
    aq1=wsum(dot4(Q1,awq));
  }else{
    float4 awx=__ldg((const float4*)(attw+128+c0));
    int base=(w-8)*16;
#pragma unroll
    for(int t=0;t<16;++t){
      int i=base+t;
      float4 hv=*(const float4*)&sH[i*128+c0];
      float d=wsum(dot4(hv,awx));
      if(lane==0) sax[i]=d;
    }
  }
  __syncthreads();

  if(w<8){
    float attb=__ldg(attbp);
    float q0=aq0+attb, q1=aq1+attb;
    float l0[4],l1[4];
    float mx0=-1e30f,mx1=-1e30f;
#pragma unroll
    for(int u=0;u<4;++u){
      int i=lane+32*u;
      int b0=(ma[u]>>lane)&1, b1=(mb[u]>>lane)&1;
      float ax=sax[i&127];
      float t0=ax+q0; t0=(t0>=0.f)?t0:0.2f*t0;
      float t1=ax+q1; t1=(t1>=0.f)?t1:0.2f*t1;
      l0[u]=b0?t0:-1e30f; mx0=fmaxf(mx0,l0[u]);
      l1[u]=b1?t1:-1e30f; mx1=fmaxf(mx1,l1[u]);
    }
    mx0=wmax(mx0); mx1=wmax(mx1);
    float Z0=0.f,Z1=0.f; float s0[4],s1[4];
#pragma unroll
    for(int u=0;u<4;++u){
      s0[u]=((ma[u]>>lane)&1)?expf(l0[u]-mx0):0.f; Z0+=s0[u];
      s1[u]=((mb[u]>>lane)&1)?expf(l1[u]-mx1):0.f; Z1+=s1[u];
    }
    Z0=wsum(Z0); Z1=wsum(Z1);
    float iz0=(jA<n)?1.f/Z0:0.f, iz1=(jB<n)?1.f/Z1:0.f;
#pragma unroll
    for(int u=0;u<4;++u){
      int i=lane+32*u;
      float v0=s0[u]*iz0, v1=s1[u]*iz1;
      sAg[jr0*132+i]=v0; sAg[jr1*132+i]=v1;
      if(i<n){
        if(jA<n) g_S[g*GS+i*128+jA]=v0;
        if(jB<n) g_S[g*GS+i*128+jB]=v1;
      }
    }
    __syncwarp();
    float4 O0={0,0,0,0},O1={0,0,0,0};
#pragma unroll
    for(int u=0;u<4;++u){
      unsigned m=ma[u]|mb[u];
      while(m){
        int b=__ffs(m)-1; m&=m-1;
        int i=32*u+b;
        float t0=sAg[jr0*132+i], t1=sAg[jr1*132+i];
        float4 hv=*(const float4*)&sH[i*128+c0];
        fma4(O0,t0,hv); fma4(O1,t1,hv);
      }
    }
    if(jA<n) *(float4*)&g_x2[g*GS+jA*128+c0]=O0;
    if(jB<n) *(float4*)&g_x2[g*GS+jB*128+c0]=O1;
    float4 w1v=__ldg((const float4*)(le1w+c0));
    float4 w2v=__ldg((const float4*)(le2w+c0));
    float4 w3v=__ldg((const float4*)(le3w+c0));
    float a0=wsum(dot4(O0,w1v)), b0=wsum(dot4(O0,w2v)), cc0=wsum(dot4(O0,w3v));
    float a1=wsum(dot4(O1,w1v)), b1=wsum(dot4(O1,w2v)), cc1=wsum(dot4(O1,w3v));
    if(lane==0){
      float l1b=__ldg(le1bp);
      if(jA<n){g_fa[g*128+jA]=a0+l1b; g_fb[g*128+jA]=b0; g_fc[g*128+jA]=cc0;}
      if(jB<n){g_fa[g*128+jB]=a1+l1b; g_fb[g*128+jB]=b1; g_fc[g*128+jB]=cc1;}
    }
  }
}

// ---------------- fused: B = (S^T A_diag) S  +  fitness finalize ----------------
__device__ void dv_fitTB(float* sm,int g,int r,int tid,const float* __restrict__ le3bp,int n){
  float* sS=sm+O_H;           // S full (i-major)
  float* sA=sm+O_W;           // A full, diag forced 1
  float* sAcol=sm+O_W+16384;  // A cols (stride 16), raw
  float* sSc=sm+O_AC;         // S cols (stride 16)
  float* sAg=sm+O_AG;
  float* sa=sm+O_SA;
  int lane=tid&31,w=tid>>5,c0=lane*4;
  const float* Ab=g_A+g*GS;
  int j0=r*16;

  for(int idx=tid;idx<16384;idx+=NT){
    int i=idx>>7;
    sS[idx]=(i<n)?__ldcg(g_S+g*GS+idx):0.f;
  }
  for(int idx=tid;idx<16384;idx+=NT){
    int i=idx>>7,m=idx&127;
    float v=(i<n&&m<n)?__ldcg(Ab+idx):0.f;
    if(i==m&&i<n) v=1.f;
    sA[idx]=v;
  }
  for(int idx=tid;idx<2048;idx+=NT){
    int i=idx>>4,jr=idx&15,j=j0+jr;
    float sv=0.f,av=0.f;
    if(i<n&&j<n){ sv=__ldcg(g_S+g*GS+i*128+j); av=__ldcg(Ab+i*128+j); }
    sSc[idx]=sv; sAcol[idx]=av;
  }
  if(tid<128) sa[tid]=(tid<n)?__ldcg(g_fa+g*128+tid):0.f;
  __syncthreads();

  if(w<8){
    int p=w;
    int jr0=2*p,jr1=jr0+1,jA=j0+jr0,jB=j0+jr1;
    // V rows: V_j[m] = sum_i S[i,j] * A_diag[i,m]  (sparse over S col nonzeros)
    unsigned ms0[4],ms1[4];
#pragma unroll
    for(int u=0;u<4;++u){
      int i=32*u+lane;
      float2 sv=*(const float2*)&sSc[i*16+jr0];
      ms0[u]=__ballot_sync(FULL,sv.x!=0.f);
      ms1[u]=__ballot_sync(FULL,sv.y!=0.f);
    }
    float4 V0={0,0,0,0},V1={0,0,0,0};
#pragma unroll
    for(int u=0;u<4;++u){
      unsigned m=ms0[u]|ms1[u];
      while(m){
        int b=__ffs(m)-1; m&=m-1;
        int i=32*u+b;
        float2 sv=*(const float2*)&sSc[i*16+jr0];
        float4 av=*(const float4*)&sA[i*128+c0];
        fma4(V0,sv.x,av); fma4(V1,sv.y,av);
      }
    }
    *(float4*)&sAg[jr0*132+c0]=V0;
    *(float4*)&sAg[jr1*132+c0]=V1;
    __syncwarp();
    // B rows: B_j[c] = sum_m V_j[m] * S[m,c]  (dense smem broadcast)
    float4 B0={0,0,0,0},B1={0,0,0,0};
    dense_bc4(sS,&sAg[jr0*132],&sAg[jr1*132],c0,B0,B1);
    if(jA<n)*(float4*)&g_B[g*GS+jA*128+c0]=B0;
    if(jB<n)*(float4*)&g_B[g*GS+jB*128+c0]=B1;
  }else{
    int p=w-8;
    int jr0=2*p,jr1=jr0+1,jA=j0+jr0,jB=j0+jr1;
    float s0=0.f,s1=0.f,d0=0.f,d1=0.f;
#pragma unroll
    for(int u=0;u<4;++u){
      int i=lane+32*u;
      float2 av=*(const float2*)&sAcol[i*16+jr0];
      if(i<n){
        if((av.x!=0.f)||(i==jA)){s0+=sa[i];d0+=1.f;}
        if((av.y!=0.f)||(i==jB)){s1+=sa[i];d1+=1.f;}
      }
    }
    s0=wsum(s0);d0=wsum(d0);s1=wsum(s1);d1=wsum(d1);
    if(lane==0){
      float l3b=__ldg(le3bp);
      if(jA<n){
        float f=s0-d0*__ldcg(g_fb+g*128+jA)+__ldcg(g_fc+g*128+jA)+l3b;
        g_fit[g*128+jA]=1.f/(1.f+expf(-f));
      }
      if(jB<n){
        float f=s1-d1*__ldcg(g_fb+g*128+jB)+__ldcg(g_fc+g*128+jB)+l3b;
        g_fit[g*128+jB]=1.f/(1.f+expf(-f));
      }
    }
  }
}

// ---------------- gather: local topk + A2 + x_out ----------------
__device__ void dv_gather(float* sm,int g,int r,int tid,float* __restrict__ hout,int n,int k){
  int* sp=(int*)(sm+O_PERM);
  if(tid<32) dv_topk_sort(sp,g,tid,n,k);
  __syncthreads();
  int i0=r*16;
  for(int idx=tid;idx<2048;idx+=NT){
    int rt=idx>>7,c=idx&127,rr=i0+rt;
    if(rr<k){
      int pj=sp[rr];
      float fv=__ldcg(g_fit+g*128+pj);
      float a2=0.f;
      if(c<k) a2=(c==rr)?1.f:__ldcg(g_B+g*GS+pj*128+sp[c]);
      g_A[g*GS+rr*128+c]=a2;
      hout[rr*128+c]=__ldcg(g_x2+g*GS+pj*128+c)*fv;
    } else if(rr<128){
      g_A[g*GS+rr*128+c]=0.f;
    }
  }
}

// ---------------- head ----------------
__device__ void dv_head(float* sm,int g,int tid,const float* __restrict__ b1,
                        const float* __restrict__ w2,const float* __restrict__ b2,
                        float* __restrict__ out){
  float* sJ=sm+O_H; float* z1=sm+O_H+704; float* z2=sm+O_H+840; float* sP=sm+O_RED;
  const float* w1t=g_w1tg+g*(640*128);
  for(int c=tid;c<640;c+=NT) sJ[c]=__ldcg(g_xs+g*640+c);
  __syncthreads();
  {
    int o=tid&127, q=tid>>7;
    float s=0.f;
    int clo=q*160;
#pragma unroll 4
    for(int c=clo;c<clo+160;++c) s=fmaf(sJ[c],__ldg(w1t+c*128+o),s);
    sP[q*128+o]=s;
  }
  __syncthreads();
  if(tid<128){
    float s=__ldg(b1+tid)+sP[tid]+sP[128+tid]+sP[256+tid]+sP[384+tid];
    z1[tid]=fmaxf(s,0.f);
  }
  __syncthreads();
  if(tid<2){
    float s2=__ldg(b2+tid);
    for(int c=0;c<128;++c) s2=fmaf(z1[c],__ldg(w2+tid*128+c),s2);
    z2[tid]=s2;
  }
  __syncthreads();
  if(tid==0){
    float m=fmaxf(z2[0],z2[1]);
    float lse=m+logf(expf(z2[0]-m)+expf(z2[1]-m));
    out[g*2+0]=z2[0]-lse;
    out[g*2+1]=z2[1]-lse;
  }
}

// ---------------- fused kernel ----------------
__global__ void __launch_bounds__(NT,1)
k_fused(const float* __restrict__ x,const int* __restrict__ ei,int E,
        const float* __restrict__ c0r,const float* __restrict__ c0t,
        const float* __restrict__ cwr,const float* __restrict__ cwt,
        const float* __restrict__ plw,const float* __restrict__ w1,
        const float* __restrict__ c0_brel,const float* __restrict__ cb_rel,
        const float* __restrict__ p_lin_b,const float* __restrict__ p_att_w,
        const float* __restrict__ p_att_b,
        const float* __restrict__ p_le1_w,const float* __restrict__ p_le1_b,
        const float* __restrict__ p_le2_w,const float* __restrict__ p_le3_w,
        const float* __restrict__ p_le3_b,
        const float* __restrict__ lin1_b,const float* __restrict__ lin2_w,
        const float* __restrict__ lin2_b,float* __restrict__ out){
  extern __shared__ float sm[];
  int g=blockIdx.x>>3,r=blockIdx.x&7,tid=threadIdx.x;
  float* hA=g_h+g*GS;
  float* hB=g_hb+g*GS;
  const float* wt=g_wtg+g*(12*GS);
  int sl=0;
  int j0=r*16;

  {
    const int TOT=12*GS+640*128;
    for(int idx=r*NT+tid; idx<TOT; idx+=NCTA*NT){
      if(idx<12*GS){
        int slot=idx>>14,e=idx&16383,c=e>>7,o=e&127;
        const float* src;int Cin;
        if(slot==0){src=c0r;Cin=64;}
        else if(slot==1){src=c0t;Cin=64;}
        else if(slot<6){src=cwr+(slot-2)*GS;Cin=128;}
        else if(slot<10){src=cwt+(slot-6)*GS;Cin=128;}
        else{src=plw+(slot-10)*GS;Cin=128;}
        g_wtg[g*(12*GS)+idx]=(c<Cin)?__ldg(src+o*Cin+c):0.f;
      }else{
        int j=idx-12*GS,c=(j)>>7,o=j&127;
        g_w1tg[g*(640*128)+j]=__ldg(w1+o*640+c);
      }
    }
  }
  for(int idx=tid;idx<2048;idx+=NT) g_A[g*GS+(j0+(idx>>7))*128+(idx&127)]=0.f;
  if(r==0) for(int i=tid;i<640;i+=NT) g_xs[g*640+i]=0.f;
  __syncthreads();
  if(tid<256){
    int e=(g*128+j0)*16+tid;
    int u=__ldg(ei+e),v=__ldg(ei+E+e);
    g_A[g*GS+(u&127)*128+(v&127)]=1.f;
  }
  gbar(g,sl++,tid);

  dv_conv(sm,g,r,tid,x+g*128*64,64,hA,wt+0*GS,wt+1*GS,c0_brel,0,128,1.f/128.f,1);
  gbar(g,sl++,tid);
  dv_conv(sm,g,r,tid,hA,128,hB,wt+2*GS,wt+6*GS,cb_rel+0,1,128,1.f/128.f,1);
  gbar(g,sl++,tid);

  // pool 1: 128 -> 103, h=hB, x_out -> hA
  dv_pqsm(sm,g,r,tid,hB,wt+10*GS,p_lin_b+0,p_att_w+0,p_att_b+0,
          p_le1_w+0,p_le1_b+0,p_le2_w+0,p_le3_w+0,128);
  gbar(g,sl++,tid);
  dv_fitTB(sm,g,r,tid,p_le3_b+0,128);
  gbar(g,sl++,tid);
  dv_gather(sm,g,r,tid,hA,128,103);
  gbar(g,sl++,tid);

  dv_conv(sm,g,r,tid,hA,128,hB,wt+3*GS,wt+7*GS,cb_rel+128,2,103,1.f/103.f,1);
  gbar(g,sl++,tid);
  dv_conv(sm,g,r,tid,hB,128,hA,wt+4*GS,wt+8*GS,cb_rel+256,3,103,1.f/103.f,1);
  gbar(g,sl++,tid);

  // pool 2: 103 -> 83, h=hA, x_out -> hB
  dv_pqsm(sm,g,r,tid,hA,wt+11*GS,p_lin_b+128,p_att_w+256,p_att_b+1,
          p_le1_w+128,p_le1_b+1,p_le2_w+128,p_le3_w+128,103);
  gbar(g,sl++,tid);
  dv_fitTB(sm,g,r,tid,p_le3_b+1,103);
  gbar(g,sl++,tid);
  dv_gather(sm,g,r,tid,hB,103,83);
  gbar(g,sl++,tid);

  dv_conv(sm,g,r,tid,hB,128,hA,wt+5*GS,wt+9*GS,cb_rel+384,4,83,1.f/83.f,0);
  gbar(g,sl++,tid);

  if(r==0) dv_head(sm,g,tid,lin1_b,lin2_w,lin2_b,out);
}

// ---------------- host ----------------
extern "C" void kernel_launch(void* const* d_in,const int* in_sizes,int n_in,
                              void* d_out,int out_size){
  const float* x       =(const float*)d_in[0];
  const int*   ei      =(const int*)  d_in[1];
  const float* c0_wrel =(const float*)d_in[2];
  const float* c0_brel =(const float*)d_in[3];
  const float* c0_wroot=(const float*)d_in[4];
  const float* cw_rel  =(const float*)d_in[5];
  const float* cb_rel  =(const float*)d_in[6];
  const float* cw_root =(const float*)d_in[7];
  const float* p_lin_w =(const float*)d_in[8];
  const float* p_lin_b =(const float*)d_in[9];
  const float* p_att_w =(const float*)d_in[10];
  const float* p_att_b =(const float*)d_in[11];
  const float* p_le1_w =(const float*)d_in[12];
  const float* p_le1_b =(const float*)d_in[13];
  const float* p_le2_w =(const float*)d_in[14];
  const float* p_le3_w =(const float*)d_in[15];
  const float* p_le3_b =(const float*)d_in[16];
  const float* lin1_w  =(const float*)d_in[17];
  const float* lin1_b  =(const float*)d_in[18];
  const float* lin2_w  =(const float*)d_in[19];
  const float* lin2_b  =(const float*)d_in[20];

  static unsigned* barp=0;
  static int inited=0;
  const size_t SMB=(size_t)SMF*4;
  if(!inited){
    cudaFuncSetAttribute(k_fused,cudaFuncAttributeMaxDynamicSharedMemorySize,(int)SMB);
    cudaGetSymbolAddress((void**)&barp,g_bar);
    inited=1;
  }
  int E=in_sizes[1]/2;
  cudaMemsetAsync(barp,0,NG*32*sizeof(unsigned));
  k_fused<<<NG*NCTA,NT,SMB>>>(x,ei,E,
                              c0_wrel,c0_wroot,cw_rel,cw_root,p_lin_w,lin1_w,
                              c0_brel,cb_rel,
                              p_lin_b,p_att_w,p_att_b,
                              p_le1_w,p_le1_b,p_le2_w,p_le3_w,p_le3_b,
                              lin1_b,lin2_w,lin2_b,(float*)d_out);
}

// round 17
// speedup vs baseline: 1.5009x; 1.5009x over previous
#include <cuda_runtime.h>
#include <math.h>

#define NG 16
#define GS 16384
#define NCTA 8
#define NT 512
#define FULL 0xffffffffu

__device__ float g_A [NG*GS];
__device__ float g_h [NG*GS];
__device__ float g_hb[NG*GS];
__device__ float g_x2[NG*GS];
__device__ float g_S [NG*GS];
__device__ float g_T [NG*GS];
__device__ float g_B [NG*GS];
__device__ float g_wtg[NG*12*GS];
__device__ float g_w1tg[NG*640*128];
__device__ float g_xs[NG*640];
__device__ float g_fit[NG*128];
__device__ float g_fa[NG*128];
__device__ float g_fb[NG*128];
__device__ float g_fc[NG*128];
__device__ int   g_perm[NG*128];
__device__ unsigned g_bar[NG*32];

// smem carve (floats)
#define O_H    0        // 16384
#define O_W    16384    // 32768 (W1 @ +0, W2 @ +16384)
#define O_AC   49152    // 2048
#define O_AG   51200    // 2112 (16 x 132)
#define O_RED  53312    // 1024
#define O_SA   54336    // 128
#define O_DEG  54464    // 32
#define O_PERM 54496    // 128 ints
#define SMF    54624

__device__ __forceinline__ void gbar(int g,int slot,int tid){
  __syncthreads();
  if (tid==0){
    __threadfence();
    unsigned* p=&g_bar[g*32+slot];
    atomicAdd(p,1u);
    unsigned v;
    do{ asm volatile("ld.acquire.gpu.u32 %0,[%1];":"=r"(v):"l"(p):"memory"); }while(v<NCTA);
  }
  __syncthreads();
}
__device__ __forceinline__ float wsum(float v){
#pragma unroll
  for(int o=16;o;o>>=1) v+=__shfl_xor_sync(FULL,v,o);
  return v;
}
__device__ __forceinline__ float wmax(float v){
#pragma unroll
  for(int o=16;o;o>>=1) v=fmaxf(v,__shfl_xor_sync(FULL,v,o));
  return v;
}
__device__ __forceinline__ void fma4(float4&o,float a,const float4 w){
  o.x=fmaf(a,w.x,o.x);o.y=fmaf(a,w.y,o.y);o.z=fmaf(a,w.z,o.z);o.w=fmaf(a,w.w,o.w);
}
__device__ __forceinline__ float dot4(const float4 a,const float4 b){
  return a.x*b.x+a.y*b.y+a.z*b.z+a.w*b.w;
}

// dense smem-broadcast matmul, float4 operand fetch (rows 16B-aligned, stride 132)
__device__ __forceinline__ void dense_bc4(const float* W,const float* g0,const float* g1,
                                          int c0,float4&O0,float4&O1){
  for(int k4=0;k4<32;++k4){
    float4 a0=*(const float4*)&g0[k4*4];
    float4 a1=*(const float4*)&g1[k4*4];
    const float* wb=&W[k4*4*128+c0];
    float4 wv;
    wv=*(const float4*)(wb     ); fma4(O0,a0.x,wv); fma4(O1,a1.x,wv);
    wv=*(const float4*)(wb+128 ); fma4(O0,a0.y,wv); fma4(O1,a1.y,wv);
    wv=*(const float4*)(wb+256 ); fma4(O0,a0.z,wv); fma4(O1,a1.z,wv);
    wv=*(const float4*)(wb+384 ); fma4(O0,a0.w,wv); fma4(O1,a1.w,wv);
  }
}

// ---------------- warp bitonic top-k (descending, ties -> lower index) ----------------
__device__ void dv_topk_sort(int g,int lane,int n,int k){
  unsigned long long key[4];
#pragma unroll
  for(int q=0;q<4;++q){
    int idx=q*32+lane;
    float f=(idx<n)?__ldcg(g_fit+g*128+idx):0.f;
    unsigned fb=__float_as_uint(f);
    key[q]=((unsigned long long)fb<<32)|(unsigned)(127-idx);
  }
  for(int size=2;size<=128;size<<=1){
    for(int stride=size>>1;stride>0;stride>>=1){
      if(stride>=32){
        int qs=stride>>5;
#pragma unroll
        for(int q=0;q<4;++q){
          if((q&qs)==0){
            int qb=q|qs;
            int idxa=q*32+lane;
            bool up=((idxa&size)!=0);
            unsigned long long a=key[q],b=key[qb];
            unsigned long long mx=(a>b)?a:b, mn=(a>b)?b:a;
            key[q]=up?mn:mx; key[qb]=up?mx:mn;
          }
        }
      }else{
#pragma unroll
        for(int q=0;q<4;++q){
          int idx=q*32+lane;
          unsigned long long pv=__shfl_xor_sync(FULL,key[q],stride);
          bool up=((idx&size)!=0);
          bool lower=((idx&stride)==0);
          bool takeMax=(lower!=up);
          unsigned long long mx=(key[q]>pv)?key[q]:pv;
          unsigned long long mn=(key[q]>pv)?pv:key[q];
          key[q]=takeMax?mx:mn;
        }
      }
    }
  }
#pragma unroll
  for(int q=0;q<4;++q){
    int pos=q*32+lane;
    if(pos<k){
      int idx=127-(int)(key[q]&0xFFFFFFFFu);
      g_perm[g*128+pos]=idx;
    }
  }
}

// ---------------- conv ----------------
__device__ void dv_conv(float* sm,int g,int r,int tid,const float* __restrict__ X,int Cin,
                        float* __restrict__ hout,const float* __restrict__ wt1,
                        const float* __restrict__ wt2,const float* __restrict__ brel,
                        int slot,int n,float invn,int wH){
  float* sH=sm+O_H; float* sW=sm+O_W; float* sAc=sm+O_AC; float* sAg=sm+O_AG;
  float* sRed=sm+O_RED; float* sDeg=sm+O_DEG;
  int lane=tid&31,w=tid>>5,c0=lane*4;
  int p=w&7,hf=w>>3;
  int j0=r*16,jr0=2*p,jr1=jr0+1,jA=j0+jr0,jB=j0+jr1;
  const float* Ab=g_A+g*GS;

  if(Cin==128&&n==128){
    for(int i4=tid;i4<4096;i4+=NT) ((float4*)sH)[i4]=__ldcg((const float4*)X+i4);
  }else{
    for(int idx=tid;idx<16384;idx+=NT){
      int i=idx>>7,c=idx&127;
      float v=0.f;
      if(i<n&&c<Cin) v=(Cin==128)?__ldcg(X+i*128+c):__ldg(X+i*64+c);
      sH[idx]=v;
    }
  }
  for(int idx=tid;idx<2048;idx+=NT){
    int i=idx>>4,jr=idx&15,j=j0+jr;
    sAc[idx]=(i<n&&j<n)?__ldcg(Ab+i*128+j):0.f;
  }
  for(int i4=tid;i4<4096;i4+=NT) ((float4*)sW)[i4]=__ldg((const float4*)wt1+i4);
  for(int i4=tid;i4<4096;i4+=NT) ((float4*)(sW+16384))[i4]=__ldg((const float4*)wt2+i4);
  __syncthreads();

  int ilo=hf*64;
  unsigned m0p[2],m1p[2],mu[2];
#pragma unroll
  for(int u=0;u<2;++u){
    int i=ilo+32*u+lane;
    float2 av=*(const float2*)&sAc[i*16+jr0];
    m0p[u]=__ballot_sync(FULL,av.x!=0.f);
    m1p[u]=__ballot_sync(FULL,av.y!=0.f);
    mu[u]=m0p[u]|m1p[u];
  }
  float cd0=(float)(__popc(m0p[0])+__popc(m0p[1]));
  float cd1=(float)(__popc(m1p[0])+__popc(m1p[1]));
  float4 A0={0,0,0,0},A1={0,0,0,0};
#pragma unroll
  for(int u=0;u<2;++u){
    unsigned m=mu[u];
    while(m){
      int b=__ffs(m)-1; m&=m-1;
      int i=ilo+32*u+b;
      float2 av=*(const float2*)&sAc[i*16+jr0];
      float4 hv=*(const float4*)&sH[i*128+c0];
      fma4(A0,av.x,hv); fma4(A1,av.y,hv);
    }
  }
  float4 H0={0,0,0,0},H1={0,0,0,0};
  if(hf==1){
    *(float4*)&sAg[jr0*132+c0]=A0;
    *(float4*)&sAg[jr1*132+c0]=A1;
    int ja=(jA<n)?jA:0,jb=(jB<n)?jB:0;
    H0=*(const float4*)&sH[ja*128+c0];
    H1=*(const float4*)&sH[jb*128+c0];
  }
  if(lane==0){ sDeg[hf*16+jr0]=cd0; sDeg[hf*16+jr1]=cd1; }
  __syncthreads();
  if(hf==0){
    float4 P0=*(const float4*)&sAg[jr0*132+c0];
    float4 P1=*(const float4*)&sAg[jr1*132+c0];
    float id0=1.f/fmaxf(sDeg[jr0]+sDeg[16+jr0],1.f);
    float id1=1.f/fmaxf(sDeg[jr1]+sDeg[16+jr1],1.f);
    A0.x=(A0.x+P0.x)*id0;A0.y=(A0.y+P0.y)*id0;A0.z=(A0.z+P0.z)*id0;A0.w=(A0.w+P0.w)*id0;
    A1.x=(A1.x+P1.x)*id1;A1.y=(A1.y+P1.y)*id1;A1.z=(A1.z+P1.z)*id1;A1.w=(A1.w+P1.w)*id1;
    *(float4*)&sAg[jr0*132+c0]=A0;
    *(float4*)&sAg[jr1*132+c0]=A1;
  }
  __syncwarp();

  float4 O0={0,0,0,0},O1={0,0,0,0};
  if(w<8){
    dense_bc4(sW,&sAg[jr0*132],&sAg[jr1*132],c0,O0,O1);
  }else{
    float hr0[4]={H0.x,H0.y,H0.z,H0.w};
    float hr1[4]={H1.x,H1.y,H1.z,H1.w};
    for(int kl=0;kl<32;++kl){
#pragma unroll
      for(int comp=0;comp<4;++comp){
        float a0=__shfl_sync(FULL,hr0[comp],kl);
        float a1=__shfl_sync(FULL,hr1[comp],kl);
        float4 wv=*(const float4*)&sW[16384+(kl*4+comp)*128+c0];
        fma4(O0,a0,wv); fma4(O1,a1,wv);
      }
    }
    *(float4*)&sAc[jr0*128+c0]=O0;
    *(float4*)&sAc[jr1*128+c0]=O1;
  }
  __syncthreads();
  if(w<8){
    float4 P0=*(const float4*)&sAc[jr0*128+c0];
    float4 P1=*(const float4*)&sAc[jr1*128+c0];
    float4 bb=__ldg((const float4*)(brel+c0));
    float4 V0,V1;
    V0.x=fmaxf(O0.x+P0.x+bb.x,0.f);V0.y=fmaxf(O0.y+P0.y+bb.y,0.f);
    V0.z=fmaxf(O0.z+P0.z+bb.z,0.f);V0.w=fmaxf(O0.w+P0.w+bb.w,0.f);
    V1.x=fmaxf(O1.x+P1.x+bb.x,0.f);V1.y=fmaxf(O1.y+P1.y+bb.y,0.f);
    V1.z=fmaxf(O1.z+P1.z+bb.z,0.f);V1.w=fmaxf(O1.w+P1.w+bb.w,0.f);
    if(jA<n){ if(wH) *(float4*)&hout[jA*128+c0]=V0; } else V0=make_float4(0,0,0,0);
    if(jB<n){ if(wH) *(float4*)&hout[jB*128+c0]=V1; } else V1=make_float4(0,0,0,0);
    float4 P; P.x=V0.x+V1.x;P.y=V0.y+V1.y;P.z=V0.z+V1.z;P.w=V0.w+V1.w;
    *(float4*)&sRed[p*128+c0]=P;
  }
  __syncthreads();
  if(tid<128){
    float s=0.f;
#pragma unroll
    for(int q=0;q<8;++q) s+=sRed[q*128+tid];
    atomicAdd(&g_xs[g*640+slot*128+tid],s*invn);
  }
}

// ---------------- fused poolq + softmax + x_new + fitness prep ----------------
__device__ void dv_pqsm(float* sm,int g,int r,int tid,const float* __restrict__ hg,
                        const float* __restrict__ wt,const float* __restrict__ linb,
                        const float* __restrict__ attw,const float* __restrict__ attbp,
                        const float* __restrict__ le1w,const float* __restrict__ le1bp,
                        const float* __restrict__ le2w,const float* __restrict__ le3w,int n){
  float* sH=sm+O_H; float* sW=sm+O_W; float* sAc=sm+O_AC; float* sAg=sm+O_AG; float* sax=sm+O_SA;
  int lane=tid&31,w=tid>>5,c0=lane*4;
  int p=w&7;
  int j0=r*16,jr0=2*p,jr1=jr0+1,jA=j0+jr0,jB=j0+jr1;
  const float* Ab=g_A+g*GS;

  for(int idx=tid;idx<16384;idx+=NT){
    int i=idx>>7;
    sH[idx]=(i<n)?__ldcg(hg+idx):0.f;
  }
  for(int idx=tid;idx<2048;idx+=NT){
    int i=idx>>4,jr=idx&15,j=j0+jr;
    sAc[idx]=(i<n&&j<n)?__ldcg(Ab+i*128+j):0.f;
  }
  for(int i4=tid;i4<4096;i4+=NT) ((float4*)sW)[i4]=__ldg((const float4*)wt+i4);
  __syncthreads();

  float aq0=0.f,aq1=0.f;
  unsigned ma[4],mb[4];
  if(w<8){
#pragma unroll
    for(int u=0;u<4;++u){
      int i=32*u+lane;
      float2 av=*(const float2*)&sAc[i*16+jr0];
      bool b0=(i<n)&&(jA<n)&&((av.x!=0.f)||(i==jA));
      bool b1=(i<n)&&(jB<n)&&((av.y!=0.f)||(i==jB));
      ma[u]=__ballot_sync(FULL,b0);
      mb[u]=__ballot_sync(FULL,b1);
    }
    float4 M0=make_float4(-1e30f,-1e30f,-1e30f,-1e30f),M1=M0;
#pragma unroll
    for(int u=0;u<4;++u){
      unsigned m=ma[u]|mb[u];
      while(m){
        int b=__ffs(m)-1; m&=m-1;
        int i=32*u+b;
        float4 hv=*(const float4*)&sH[i*128+c0];
        if((ma[u]>>b)&1){M0.x=fmaxf(M0.x,hv.x);M0.y=fmaxf(M0.y,hv.y);M0.z=fmaxf(M0.z,hv.z);M0.w=fmaxf(M0.w,hv.w);}
        if((mb[u]>>b)&1){M1.x=fmaxf(M1.x,hv.x);M1.y=fmaxf(M1.y,hv.y);M1.z=fmaxf(M1.z,hv.z);M1.w=fmaxf(M1.w,hv.w);}
      }
    }
    *(float4*)&sAg[jr0*132+c0]=M0;
    *(float4*)&sAg[jr1*132+c0]=M1;
    __syncwarp();
    float4 Q0={0,0,0,0},Q1={0,0,0,0};
    dense_bc4(sW,&sAg[jr0*132],&sAg[jr1*132],c0,Q0,Q1);
    float4 lb=__ldg((const float4*)(linb+c0));
    Q0.x+=lb.x;Q0.y+=lb.y;Q0.z+=lb.z;Q0.w+=lb.w;
    Q1.x+=lb.x;Q1.y+=lb.y;Q1.z+=lb.z;Q1.w+=lb.w;
    float4 awq=__ldg((const float4*)(attw+c0));
    aq0=wsum(dot4(Q0,awq));
    aq1=wsum(dot4(Q1,awq));
  }else{
    float4 awx=__ldg((const float4*)(attw+128+c0));
    int base=(w-8)*16;
#pragma unroll
    for(int t=0;t<16;++t){
      int i=base+t;
      float4 hv=*(const float4*)&sH[i*128+c0];
      float d=wsum(dot4(hv,awx));
      if(lane==0) sax[i]=d;
    }
  }
  __syncthreads();

  if(w<8){
    float attb=__ldg(attbp);
    float q0=aq0+attb, q1=aq1+attb;
    float l0[4],l1[4];
    float mx0=-1e30f,mx1=-1e30f;
#pragma unroll
    for(int u=0;u<4;++u){
      int i=lane+32*u;
      int b0=(ma[u]>>lane)&1, b1=(mb[u]>>lane)&1;
      float ax=sax[i&127];
      float t0=ax+q0; t0=(t0>=0.f)?t0:0.2f*t0;
      float t1=ax+q1; t1=(t1>=0.f)?t1:0.2f*t1;
      l0[u]=b0?t0:-1e30f; mx0=fmaxf(mx0,l0[u]);
      l1[u]=b1?t1:-1e30f; mx1=fmaxf(mx1,l1[u]);
    }
    mx0=wmax(mx0); mx1=wmax(mx1);
    float Z0=0.f,Z1=0.f; float s0[4],s1[4];
#pragma unroll
    for(int u=0;u<4;++u){
      s0[u]=((ma[u]>>lane)&1)?expf(l0[u]-mx0):0.f; Z0+=s0[u];
      s1[u]=((mb[u]>>lane)&1)?expf(l1[u]-mx1):0.f; Z1+=s1[u];
    }
    Z0=wsum(Z0); Z1=wsum(Z1);
    float iz0=(jA<n)?1.f/Z0:0.f, iz1=(jB<n)?1.f/Z1:0.f;
#pragma unroll
    for(int u=0;u<4;++u){
      int i=lane+32*u;
      float v0=s0[u]*iz0, v1=s1[u]*iz1;
      sAg[jr0*132+i]=v0; sAg[jr1*132+i]=v1;
      if(i<n){
        if(jA<n) g_S[g*GS+i*128+jA]=v0;
        if(jB<n) g_S[g*GS+i*128+jB]=v1;
      }
    }
    __syncwarp();
    float4 O0={0,0,0,0},O1={0,0,0,0};
#pragma unroll
    for(int u=0;u<4;++u){
      unsigned m=ma[u]|mb[u];
      while(m){
        int b=__ffs(m)-1; m&=m-1;
        int i=32*u+b;
        float t0=sAg[jr0*132+i], t1=sAg[jr1*132+i];
        float4 hv=*(const float4*)&sH[i*128+c0];
        fma4(O0,t0,hv); fma4(O1,t1,hv);
      }
    }
    if(jA<n) *(float4*)&g_x2[g*GS+jA*128+c0]=O0;
    if(jB<n) *(float4*)&g_x2[g*GS+jB*128+c0]=O1;
    float4 w1v=__ldg((const float4*)(le1w+c0));
    float4 w2v=__ldg((const float4*)(le2w+c0));
    float4 w3v=__ldg((const float4*)(le3w+c0));
    float a0=wsum(dot4(O0,w1v)), b0=wsum(dot4(O0,w2v)), cc0=wsum(dot4(O0,w3v));
    float a1=wsum(dot4(O1,w1v)), b1=wsum(dot4(O1,w2v)), cc1=wsum(dot4(O1,w3v));
    if(lane==0){
      float l1b=__ldg(le1bp);
      if(jA<n){g_fa[g*128+jA]=a0+l1b; g_fb[g*128+jA]=b0; g_fc[g*128+jA]=cc0;}
      if(jB<n){g_fa[g*128+jB]=a1+l1b; g_fb[g*128+jB]=b1; g_fc[g*128+jB]=cc1;}
    }
  }
}

// ---------------- T = A_diag @ S  +  fitness finalize ----------------
__device__ void dv_fitT(float* sm,int g,int r,int tid,const float* __restrict__ le3bp,int n){
  float* sS=sm+O_H; float* sAr=sm+O_W; float* sAc=sm+O_AC; float* sa=sm+O_SA;
  int lane=tid&31,w=tid>>5,c0=lane*4;
  int p=w&7;
  int j0=r*16,jr0=2*p,jr1=jr0+1,jA=j0+jr0,jB=j0+jr1;
  const float* Ab=g_A+g*GS;
  for(int idx=tid;idx<16384;idx+=NT){
    int i=idx>>7;
    sS[idx]=(i<n)?__ldcg(g_S+g*GS+idx):0.f;
  }
  for(int idx=tid;idx<2048;idx+=NT){
    int it=idx>>7,m=idx&127,i=j0+it;
    float v=(i<n&&m<n)?__ldcg(Ab+i*128+m):0.f;
    if(m==i&&i<n) v=1.f;
    sAr[it*132+m]=v;
  }
  for(int idx=tid;idx<2048;idx+=NT){
    int i=idx>>4,jr=idx&15,j=j0+jr;
    sAc[idx]=(i<n&&j<n)?__ldcg(Ab+i*128+j):0.f;
  }
  if(tid<128) sa[tid]=(tid<n)?__ldcg(g_fa+g*128+tid):0.f;
  __syncthreads();
  if(w<8){
    const float* a0p=&sAr[jr0*132]; const float* a1p=&sAr[jr1*132];
    unsigned ra[4],rb[4];
#pragma unroll
    for(int u=0;u<4;++u){
      int m=32*u+lane;
      ra[u]=__ballot_sync(FULL,a0p[m]!=0.f);
      rb[u]=__ballot_sync(FULL,a1p[m]!=0.f);
    }
    float4 T0={0,0,0,0},T1={0,0,0,0};
#pragma unroll
    for(int u=0;u<4;++u){
      unsigned m=ra[u]|rb[u];
      while(m){
        int b=__ffs(m)-1; m&=m-1;
        int mm=32*u+b;
        float a0=a0p[mm],a1=a1p[mm];
        float4 sv=*(const float4*)&sS[mm*128+c0];
        fma4(T0,a0,sv); fma4(T1,a1,sv);
      }
    }
    if(jA<n) *(float4*)&g_T[g*GS+jA*128+c0]=T0;
    if(jB<n) *(float4*)&g_T[g*GS+jB*128+c0]=T1;
    float s0=0.f,s1=0.f,d0=0.f,d1=0.f;
#pragma unroll
    for(int u=0;u<4;++u){
      int i=lane+32*u;
      float2 av=*(const float2*)&sAc[i*16+jr0];
      if(i<n){
        if((av.x!=0.f)||(i==jA)){s0+=sa[i];d0+=1.f;}
        if((av.y!=0.f)||(i==jB)){s1+=sa[i];d1+=1.f;}
      }
    }
    s0=wsum(s0);d0=wsum(d0);s1=wsum(s1);d1=wsum(d1);
    if(lane==0){
      float l3b=__ldg(le3bp);
      if(jA<n){
        float f=s0-d0*__ldcg(g_fb+g*128+jA)+__ldcg(g_fc+g*128+jA)+l3b;
        g_fit[g*128+jA]=1.f/(1.f+expf(-f));
      }
      if(jB<n){
        float f=s1-d1*__ldcg(g_fb+g*128+jB)+__ldcg(g_fc+g*128+jB)+l3b;
        g_fit[g*128+jB]=1.f/(1.f+expf(-f));
      }
    }
  }
}

// ---------------- B = S^T @ T  +  top-k (bitonic) ----------------
__device__ void dv_B(float* sm,int g,int r,int tid,int n,int k){
  float* sT=sm+O_H; float* sSc=sm+O_AC;
  int lane=tid&31,w=tid>>5,c0=lane*4;
  int p=w&7;
  int j0=r*16,jr0=2*p,jr1=jr0+1,jA=j0+jr0,jB=j0+jr1;
  for(int idx=tid;idx<16384;idx+=NT){
    int i=idx>>7;
    sT[idx]=(i<n)?__ldcg(g_T+g*GS+idx):0.f;
  }
  for(int idx=tid;idx<2048;idx+=NT){
    int i=idx>>4,jr=idx&15,j=j0+jr;
    sSc[idx]=(i<n&&j<n)?__ldcg(g_S+g*GS+i*128+j):0.f;
  }
  __syncthreads();
  if(w<8){
    unsigned sa2[4],sb2[4];
#pragma unroll
    for(int u=0;u<4;++u){
      int i=32*u+lane;
      float2 sv=*(const float2*)&sSc[i*16+jr0];
      sa2[u]=__ballot_sync(FULL,sv.x!=0.f);
      sb2[u]=__ballot_sync(FULL,sv.y!=0.f);
    }
    float4 B0={0,0,0,0},B1={0,0,0,0};
#pragma unroll
    for(int u=0;u<4;++u){
      unsigned m=sa2[u]|sb2[u];
      while(m){
        int b=__ffs(m)-1; m&=m-1;
        int i=32*u+b;
        float2 sv=*(const float2*)&sSc[i*16+jr0];
        float4 tv=*(const float4*)&sT[i*128+c0];
        fma4(B0,sv.x,tv); fma4(B1,sv.y,tv);
      }
    }
    if(jA<n)*(float4*)&g_B[g*GS+jA*128+c0]=B0;
    if(jB<n)*(float4*)&g_B[g*GS+jB*128+c0]=B1;
  }
  if(r==0&&w==8){
    dv_topk_sort(g,lane,n,k);
  }
}

// ---------------- gather: A2 + x_out ----------------
__device__ void dv_gather(float* sm,int g,int r,int tid,float* __restrict__ hout,int n,int k){
  int* sp=(int*)(sm+O_PERM);
  if(tid<128) sp[tid]=(tid<k)?__ldcg(g_perm+g*128+tid):0;
  __syncthreads();
  int i0=r*16;
  for(int idx=tid;idx<2048;idx+=NT){
    int rt=idx>>7,c=idx&127,rr=i0+rt;
    if(rr<k){
      int pj=sp[rr];
      float fv=__ldcg(g_fit+g*128+pj);
      float a2=0.f;
      if(c<k) a2=(c==rr)?1.f:__ldcg(g_B+g*GS+pj*128+sp[c]);
      g_A[g*GS+rr*128+c]=a2;
      hout[rr*128+c]=__ldcg(g_x2+g*GS+pj*128+c)*fv;
    } else if(rr<128){
      g_A[g*GS+rr*128+c]=0.f;
    }
  }
}

// ---------------- head ----------------
__device__ void dv_head(float* sm,int g,int tid,const float* __restrict__ b1,
                        const float* __restrict__ w2,const float* __restrict__ b2,
                        float* __restrict__ out){
  float* sJ=sm+O_H; float* z1=sm+O_H+704; float* z2=sm+O_H+840; float* sP=sm+O_RED;
  const float* w1t=g_w1tg+g*(640*128);
  for(int c=tid;c<640;c+=NT) sJ[c]=__ldcg(g_xs+g*640+c);
  __syncthreads();
  {
    int o=tid&127, q=tid>>7;
    float s=0.f;
    int clo=q*160;
#pragma unroll 4
    for(int c=clo;c<clo+160;++c) s=fmaf(sJ[c],__ldg(w1t+c*128+o),s);
    sP[q*128+o]=s;
  }
  __syncthreads();
  if(tid<128){
    float s=__ldg(b1+tid)+sP[tid]+sP[128+tid]+sP[256+tid]+sP[384+tid];
    z1[tid]=fmaxf(s,0.f);
  }
  __syncthreads();
  if(tid<2){
    float s2=__ldg(b2+tid);
    for(int c=0;c<128;++c) s2=fmaf(z1[c],__ldg(w2+tid*128+c),s2);
    z2[tid]=s2;
  }
  __syncthreads();
  if(tid==0){
    float m=fmaxf(z2[0],z2[1]);
    float lse=m+logf(expf(z2[0]-m)+expf(z2[1]-m));
    out[g*2+0]=z2[0]-lse;
    out[g*2+1]=z2[1]-lse;
  }
}

// ---------------- fused kernel ----------------
__global__ void __launch_bounds__(NT,1)
k_fused(const float* __restrict__ x,const int* __restrict__ ei,int E,
        const float* __restrict__ c0r,const float* __restrict__ c0t,
        const float* __restrict__ cwr,const float* __restrict__ cwt,
        const float* __restrict__ plw,const float* __restrict__ w1,
        const float* __restrict__ c0_brel,const float* __restrict__ cb_rel,
        const float* __restrict__ p_lin_b,const float* __restrict__ p_att_w,
        const float* __restrict__ p_att_b,
        const float* __restrict__ p_le1_w,const float* __restrict__ p_le1_b,
        const float* __restrict__ p_le2_w,const float* __restrict__ p_le3_w,
        const float* __restrict__ p_le3_b,
        const float* __restrict__ lin1_b,const float* __restrict__ lin2_w,
        const float* __restrict__ lin2_b,float* __restrict__ out){
  extern __shared__ float sm[];
  int g=blockIdx.x>>3,r=blockIdx.x&7,tid=threadIdx.x;
  float* hA=g_h+g*GS;
  float* hB=g_hb+g*GS;
  const float* wt=g_wtg+g*(12*GS);
  int sl=0;
  int j0=r*16;

  {
    const int TOT=12*GS+640*128;
    for(int idx=r*NT+tid; idx<TOT; idx+=NCTA*NT){
      if(idx<12*GS){
        int slot=idx>>14,e=idx&16383,c=e>>7,o=e&127;
        const float* src;int Cin;
        if(slot==0){src=c0r;Cin=64;}
        else if(slot==1){src=c0t;Cin=64;}
        else if(slot<6){src=cwr+(slot-2)*GS;Cin=128;}
        else if(slot<10){src=cwt+(slot-6)*GS;Cin=128;}
        else{src=plw+(slot-10)*GS;Cin=128;}
        g_wtg[g*(12*GS)+idx]=(c<Cin)?__ldg(src+o*Cin+c):0.f;
      }else{
        int j=idx-12*GS,c=(j)>>7,o=j&127;
        g_w1tg[g*(640*128)+j]=__ldg(w1+o*640+c);
      }
    }
  }
  for(int idx=tid;idx<2048;idx+=NT) g_A[g*GS+(j0+(idx>>7))*128+(idx&127)]=0.f;
  if(r==0) for(int i=tid;i<640;i+=NT) g_xs[g*640+i]=0.f;
  __syncthreads();
  if(tid<256){
    int e=(g*128+j0)*16+tid;
    int u=__ldg(ei+e),v=__ldg(ei+E+e);
    g_A[g*GS+(u&127)*128+(v&127)]=1.f;
  }
  gbar(g,sl++,tid);

  dv_conv(sm,g,r,tid,x+g*128*64,64,hA,wt+0*GS,wt+1*GS,c0_brel,0,128,1.f/128.f,1);
  gbar(g,sl++,tid);
  dv_conv(sm,g,r,tid,hA,128,hB,wt+2*GS,wt+6*GS,cb_rel+0,1,128,1.f/128.f,1);
  gbar(g,sl++,tid);

  // pool 1: 128 -> 103, h=hB, x_out -> hA
  dv_pqsm(sm,g,r,tid,hB,wt+10*GS,p_lin_b+0,p_att_w+0,p_att_b+0,
          p_le1_w+0,p_le1_b+0,p_le2_w+0,p_le3_w+0,128);
  gbar(g,sl++,tid);
  dv_fitT(sm,g,r,tid,p_le3_b+0,128);
  gbar(g,sl++,tid);
  dv_B(sm,g,r,tid,128,103);
  gbar(g,sl++,tid);
  dv_gather(sm,g,r,tid,hA,128,103);
  gbar(g,sl++,tid);

  dv_conv(sm,g,r,tid,hA,128,hB,wt+3*GS,wt+7*GS,cb_rel+128,2,103,1.f/103.f,1);
  gbar(g,sl++,tid);
  dv_conv(sm,g,r,tid,hB,128,hA,wt+4*GS,wt+8*GS,cb_rel+256,3,103,1.f/103.f,1);
  gbar(g,sl++,tid);

  // pool 2: 103 -> 83, h=hA, x_out -> hB
  dv_pqsm(sm,g,r,tid,hA,wt+11*GS,p_lin_b+128,p_att_w+256,p_att_b+1,
          p_le1_w+128,p_le1_b+1,p_le2_w+128,p_le3_w+128,103);
  gbar(g,sl++,tid);
  dv_fitT(sm,g,r,tid,p_le3_b+1,103);
  gbar(g,sl++,tid);
  dv_B(sm,g,r,tid,103,83);
  gbar(g,sl++,tid);
  dv_gather(sm,g,r,tid,hB,103,83);
  gbar(g,sl++,tid);

  dv_conv(sm,g,r,tid,hB,128,hA,wt+5*GS,wt+9*GS,cb_rel+384,4,83,1.f/83.f,0);
  gbar(g,sl++,tid);

  if(r==0) dv_head(sm,g,tid,lin1_b,lin2_w,lin2_b,out);
}

// ---------------- host ----------------
extern "C" void kernel_launch(void* const* d_in,const int* in_sizes,int n_in,
                              void* d_out,int out_size){
  const float* x       =(const float*)d_in[0];
  const int*   ei      =(const int*)  d_in[1];
  const float* c0_wrel =(const float*)d_in[2];
  const float* c0_brel =(const float*)d_in[3];
  const float* c0_wroot=(const float*)d_in[4];
  const float* cw_rel  =(const float*)d_in[5];
  const float* cb_rel  =(const float*)d_in[6];
  const float* cw_root =(const float*)d_in[7];
  const float* p_lin_w =(const float*)d_in[8];
  const float* p_lin_b =(const float*)d_in[9];
  const float* p_att_w =(const float*)d_in[10];
  const float* p_att_b =(const float*)d_in[11];
  const float* p_le1_w =(const float*)d_in[12];
  const float* p_le1_b =(const float*)d_in[13];
  const float* p_le2_w =(const float*)d_in[14];
  const float* p_le3_w =(const float*)d_in[15];
  const float* p_le3_b =(const float*)d_in[16];
  const float* lin1_w  =(const float*)d_in[17];
  const float* lin1_b  =(const float*)d_in[18];
  const float* lin2_w  =(const float*)d_in[19];
  const float* lin2_b  =(const float*)d_in[20];

  static unsigned* barp=0;
  static int inited=0;
  const size_t SMB=(size_t)SMF*4;
  if(!inited){
    cudaFuncSetAttribute(k_fused,cudaFuncAttributeMaxDynamicSharedMemorySize,(int)SMB);
    cudaGetSymbolAddress((void**)&barp,g_bar);
    inited=1;
  }
  int E=in_sizes[1]/2;
  cudaMemsetAsync(barp,0,NG*32*sizeof(unsigned));
  k_fused<<<NG*NCTA,NT,SMB>>>(x,ei,E,
                              c0_wrel,c0_wroot,cw_rel,cw_root,p_lin_w,lin1_w,
                              c0_brel,cb_rel,
                              p_lin_b,p_att_w,p_att_b,
                              p_le1_w,p_le1_b,p_le2_w,p_le3_w,p_le3_b,
                              lin1_b,lin2_w,lin2_b,(float*)d_out);
}